// round 16
// baseline (speedup 1.0000x reference)
#include <cuda_runtime.h>
#include <cuda_fp16.h>
#include <cstdint>
#include <math.h>

#define NB 128
#define NL 4096
#define ND 128
#define NTILES 4096   // 128-row L tiles

// ---------------- scratch ----------------
__device__ float g_qb[NB * ND];
__device__ float g_scores[NB * NL];

__device__ __forceinline__ uint32_t smem_u32(const void* p) {
    uint32_t a;
    asm("{ .reg .u64 t; cvta.to.shared.u64 t, %1; cvt.u32.u64 %0, t; }" : "=r"(a) : "l"(p));
    return a;
}
__device__ __forceinline__ void ldsm_x4(uint32_t& r0, uint32_t& r1, uint32_t& r2, uint32_t& r3,
                                        uint32_t addr) {
    asm volatile("ldmatrix.sync.aligned.m8n8.x4.shared.b16 {%0,%1,%2,%3}, [%4];"
                 : "=r"(r0), "=r"(r1), "=r"(r2), "=r"(r3) : "r"(addr));
}
__device__ __forceinline__ void mma16816h(float* c, const uint32_t* a, const uint32_t* b) {
    asm volatile("mma.sync.aligned.m16n8k16.row.col.f32.f16.f16.f32 "
                 "{%0,%1,%2,%3}, {%4,%5,%6,%7}, {%8,%9}, {%0,%1,%2,%3};"
                 : "+f"(c[0]), "+f"(c[1]), "+f"(c[2]), "+f"(c[3])
                 : "r"(a[0]), "r"(a[1]), "r"(a[2]), "r"(a[3]), "r"(b[0]), "r"(b[1]));
}
__device__ __forceinline__ float fast_pow(float x, float e) {
    float l, r;
    asm("lg2.approx.f32 %0, %1;" : "=f"(l) : "f"(x));
    l *= e;
    asm("ex2.approx.f32 %0, %1;" : "=f"(r) : "f"(l));
    return r;
}
__device__ __forceinline__ uint32_t pack_h2(float x, float y) {
    __half h0 = __float2half_rn(x), h1 = __float2half_rn(y);
    return ((uint32_t)__half_as_ushort(h1) << 16) | __half_as_ushort(h0);
}

// ============ kernel 0: qb = Wr2·(Wf target + b) + bias_r ============
__global__ __launch_bounds__(512, 1)
void k_prep(const float* __restrict__ target, const float* __restrict__ Wf_w,
            const float* __restrict__ Wf_b, const float* __restrict__ Wr2,
            const float* __restrict__ bias_r) {
    int bx = blockIdx.x, t = threadIdx.x;
    int lane = t & 31, w = t >> 5;
    __shared__ float q[64];
    float4 tg4 = ((const float4*)(target + bx * ND))[lane];
    #pragma unroll
    for (int r = 0; r < 4; r++) {
        int e = w + r * 16;
        float4 wf = ((const float4*)(Wf_w + e * ND))[lane];
        float p = tg4.x * wf.x + tg4.y * wf.y + tg4.z * wf.z + tg4.w * wf.w;
        #pragma unroll
        for (int o = 16; o; o >>= 1) p += __shfl_xor_sync(0xFFFFFFFFu, p, o);
        if (lane == 0) q[e] = p + Wf_b[e];
    }
    __syncthreads();
    float2 q2 = ((const float2*)q)[lane];
    #pragma unroll
    for (int r = 0; r < 8; r++) {
        int d = w + r * 16;
        float2 w2 = ((const float2*)(Wr2 + d * 64))[lane];
        float p = q2.x * w2.x + q2.y * w2.y;
        #pragma unroll
        for (int o = 16; o; o >>= 1) p += __shfl_xor_sync(0xFFFFFFFFu, p, o);
        if (lane == 0) g_qb[bx * ND + d] = p + bias_r[d];
    }
}

// ============ kernel 1: persistent SINGLE-fp16 GEMM (approx scores) ============
// 512 threads (16 warps). Warp tile 32x32 (wr=w>>2, wc=w&3). 128-row L tiles.
#define ROWB 272
#define SA    0
#define SB_HI 34816
#define SM_PART 69632
#define SM_W3   71680
#define SM_TOTAL 72192

__device__ __forceinline__ void ldg_tile(float4* v, const float* __restrict__ R,
                                         int tile, int tid) {
    int b = tile >> 5, l0 = (tile & 31) << 7;
    const float4* src = (const float4*)(R + ((size_t)b * NL + l0) * ND);
    #pragma unroll
    for (int i = 0; i < 8; i++) v[i] = src[tid + i * 512];
}
__device__ __forceinline__ void cvt_store(char* smem, const float4* v, int tid) {
    #pragma unroll
    for (int i = 0; i < 8; i++) {
        int idx = tid + i * 512;
        int row = idx >> 5, c4 = idx & 31;
        float4 x = v[i];
        uint2 hp;
        hp.x = pack_h2(x.x, x.y);
        hp.y = pack_h2(x.z, x.w);
        *(uint2*)(smem + SA + row * ROWB + c4 * 8) = hp;
    }
}

__global__ __launch_bounds__(512, 1)
void k_gemm(const float* __restrict__ R, const float* __restrict__ Wr1,
            const float* __restrict__ Wr3) {
    extern __shared__ char smem[];
    uint32_t sb = smem_u32(smem);
    int tid = threadIdx.x, lane = tid & 31, w = tid >> 5;
    int wr = w >> 2, wc = w & 3;

    // ---- B tile (fp16 of Wr1) once per CTA ----
    {
        const float4* src = (const float4*)Wr1;
        #pragma unroll
        for (int i = 0; i < 8; i++) {
            int idx = tid + i * 512;
            int row = idx >> 5, c4 = idx & 31;
            float4 x = src[idx];
            uint2 hp;
            hp.x = pack_h2(x.x, x.y);
            hp.y = pack_h2(x.z, x.w);
            *(uint2*)(smem + SB_HI + row * ROWB + c4 * 8) = hp;
        }
        if (tid < ND) ((float*)(smem + SM_W3))[tid] = Wr3[tid];
    }

    uint32_t a_p = sb + SA + (wr * 32 + (lane & 15)) * ROWB + (lane >> 4) * 16;
    uint32_t b_p = sb + SB_HI + (wc * 32 + (lane >> 4) * 8 + (lane & 7)) * ROWB
                   + ((lane >> 3) & 1) * 16;

    int stride = gridDim.x;
    int t = blockIdx.x;
    float4 v[8];
    if (t < NTILES) {
        ldg_tile(v, R, t, tid);
        cvt_store(smem, v, tid);
    }

    while (t < NTILES) {
        __syncthreads();
        int tn = t + stride;
        if (tn < NTILES) ldg_tile(v, R, tn, tid);

        int b = t >> 5, l0 = (t & 31) << 7;

        float acc[2][4][4];
        #pragma unroll
        for (int mt = 0; mt < 2; mt++)
            #pragma unroll
            for (int nt = 0; nt < 4; nt++)
                #pragma unroll
                for (int k = 0; k < 4; k++) acc[mt][nt][k] = 0.0f;

        #pragma unroll
        for (int ks = 0; ks < 8; ks++) {
            uint32_t bh[4][2];
            ldsm_x4(bh[0][0], bh[0][1], bh[1][0], bh[1][1], b_p + ks * 32);
            ldsm_x4(bh[2][0], bh[2][1], bh[3][0], bh[3][1], b_p + 16 * ROWB + ks * 32);
            #pragma unroll
            for (int mt = 0; mt < 2; mt++) {
                uint32_t a4[4];
                ldsm_x4(a4[0], a4[1], a4[2], a4[3], a_p + mt * 16 * ROWB + ks * 32);
                #pragma unroll
                for (int nt = 0; nt < 4; nt++)
                    mma16816h(acc[mt][nt], a4, bh[nt]);
            }
        }

        // epilogue: approx score[m] = sum_c relu(h+qb)*w3
        {
            const float* w3s = (const float*)(smem + SM_W3);
            float* part = (float*)(smem + SM_PART);
            const float* qbb = g_qb + b * ND;
            int c0base = wc * 32 + (lane & 3) * 2;
            #pragma unroll
            for (int mt = 0; mt < 2; mt++) {
                float vlo = 0.0f, vhi = 0.0f;
                #pragma unroll
                for (int nt = 0; nt < 4; nt++) {
                    int c0 = c0base + nt * 8, c1 = c0 + 1;
                    float q0 = __ldg(qbb + c0), q1 = __ldg(qbb + c1);
                    float t0 = w3s[c0], t1 = w3s[c1];
                    vlo += fmaxf(acc[mt][nt][0] + q0, 0.0f) * t0
                         + fmaxf(acc[mt][nt][1] + q1, 0.0f) * t1;
                    vhi += fmaxf(acc[mt][nt][2] + q0, 0.0f) * t0
                         + fmaxf(acc[mt][nt][3] + q1, 0.0f) * t1;
                }
                vlo += __shfl_xor_sync(0xFFFFFFFFu, vlo, 1);
                vlo += __shfl_xor_sync(0xFFFFFFFFu, vlo, 2);
                vhi += __shfl_xor_sync(0xFFFFFFFFu, vhi, 1);
                vhi += __shfl_xor_sync(0xFFFFFFFFu, vhi, 2);
                if ((lane & 3) == 0) {
                    int rlo = wr * 32 + mt * 16 + (lane >> 2);
                    part[rlo * 4 + wc] = vlo;
                    part[(rlo + 8) * 4 + wc] = vhi;
                }
            }
        }
        __syncthreads();
        if (tid < 128) {
            const float* part = (const float*)(smem + SM_PART);
            float s = part[tid * 4] + part[tid * 4 + 1] + part[tid * 4 + 2] + part[tid * 4 + 3];
            g_scores[b * NL + l0 + tid] = s;
        }
        if (tn < NTILES) cvt_store(smem, v, tid);
        t = tn;
    }
}

// ============ kernel 2: candidate select + EXACT fp32 recompute + entmax + sparse sum ============
// dynamic smem layout (bytes):
//   W1T (transposed Wr1, row pad 132 floats): 0      .. 67584
//   cval: 67584 .. 83968   cidx: 83968 .. 92160   rrow: 92160 .. 100352
//   qbs: 100352  w3s: 100864  part: 101376 .. 103424
#define E_W1T  0
#define E_CVAL 67584
#define E_CIDX 83968
#define E_RROW 92160
#define E_QBS  100352
#define E_W3S  100864
#define E_PART 101376
#define E_TOTAL 103424
#define MARGIN 0.1f

__global__ __launch_bounds__(512, 1)
void k_entmax(const float* __restrict__ R, const float* __restrict__ alpha,
              const float* __restrict__ Wr1, const float* __restrict__ Wr3,
              float* __restrict__ out) {
    extern __shared__ char esm[];
    float* W1T = (float*)(esm + E_W1T);
    float* cval = (float*)(esm + E_CVAL);
    unsigned short* cidx = (unsigned short*)(esm + E_CIDX);
    float* rrow = (float*)(esm + E_RROW);
    float* qbs = (float*)(esm + E_QBS);
    float* w3s = (float*)(esm + E_W3S);
    float* part = (float*)(esm + E_PART);
    __shared__ float red[16];
    __shared__ int cnt;

    int b = blockIdx.x, t = threadIdx.x;
    int lane = t & 31, w = t >> 5;
    float am1 = alpha[b] - 1.0f;
    float inv = 1.0f / am1;

    if (t == 0) cnt = 0;
    // W1T[k*132+d] = Wr1[d*128+k]
    #pragma unroll
    for (int i = 0; i < 32; i++) {
        int idx = t + i * 512;
        int d = idx >> 7, k = idx & 127;
        W1T[k * 132 + d] = Wr1[idx];
    }
    if (t < ND) { qbs[t] = g_qb[b * ND + t]; w3s[t] = Wr3[t]; }

    // approx Xs: max + widened candidate selection
    float v[8];
    float mx = -3.4e38f;
    #pragma unroll
    for (int i = 0; i < 8; i++) {
        v[i] = g_scores[b * NL + t + i * 512] * am1;
        mx = fmaxf(mx, v[i]);
    }
    #pragma unroll
    for (int o = 16; o; o >>= 1) mx = fmaxf(mx, __shfl_xor_sync(0xFFFFFFFFu, mx, o));
    if (lane == 0) red[w] = mx;
    __syncthreads();
    mx = red[0];
    #pragma unroll
    for (int i = 1; i < 16; i++) mx = fmaxf(mx, red[i]);
    __syncthreads();

    float thr = mx - 1.0f - MARGIN;
    #pragma unroll
    for (int i = 0; i < 8; i++) {
        bool p = v[i] > thr;
        unsigned m = __ballot_sync(0xFFFFFFFFu, p);
        int base = 0;
        if (lane == 0 && m) base = atomicAdd(&cnt, __popc(m));
        base = __shfl_sync(0xFFFFFFFFu, base, 0);
        if (p) cidx[base + __popc(m & ((1u << lane) - 1u))] = (unsigned short)(t + i * 512);
    }
    __syncthreads();
    int K = cnt;

    // ---- exact fp32 recompute of candidate scores (warp per candidate) ----
    const float* Rb = R + (size_t)b * NL * ND;
    for (int j = w; j < K; j += 16) {
        int l = cidx[j];
        float4 rv = ((const float4*)(Rb + (size_t)l * ND))[lane];
        ((float4*)(rrow + w * 128))[lane] = rv;
        __syncwarp();
        int d4 = lane * 4;
        float a0 = qbs[d4], a1 = qbs[d4 + 1], a2 = qbs[d4 + 2], a3 = qbs[d4 + 3];
        const float* rr = rrow + w * 128;
        #pragma unroll 8
        for (int k = 0; k < 128; k++) {
            float rk = rr[k];
            float4 wv = *(const float4*)(W1T + k * 132 + d4);
            a0 = fmaf(rk, wv.x, a0);
            a1 = fmaf(rk, wv.y, a1);
            a2 = fmaf(rk, wv.z, a2);
            a3 = fmaf(rk, wv.w, a3);
        }
        float s = fmaxf(a0, 0.0f) * w3s[d4] + fmaxf(a1, 0.0f) * w3s[d4 + 1]
                + fmaxf(a2, 0.0f) * w3s[d4 + 2] + fmaxf(a3, 0.0f) * w3s[d4 + 3];
        #pragma unroll
        for (int o = 16; o; o >>= 1) s += __shfl_xor_sync(0xFFFFFFFFu, s, o);
        if (lane == 0) cval[j] = s * am1;     // exact Xs
        __syncwarp();
    }
    __syncthreads();

    // exact max over candidates (true global max is guaranteed in the set)
    float m2 = -3.4e38f;
    for (int j = t; j < K; j += 512) m2 = fmaxf(m2, cval[j]);
    #pragma unroll
    for (int o = 16; o; o >>= 1) m2 = fmaxf(m2, __shfl_xor_sync(0xFFFFFFFFu, m2, o));
    if (lane == 0) red[w] = m2;
    __syncthreads();
    mx = red[0];
    #pragma unroll
    for (int i = 1; i < 16; i++) mx = fmaxf(mx, red[i]);
    __syncthreads();

    // bisection (reference trajectory) on exact candidate Xs
    float tau_lo = mx - 1.0f;
    float tau_hi = mx - exp2f(-12.0f * am1);
    float dm = tau_hi - tau_lo;

    float s = 0.0f;
    for (int j = t; j < K; j += 512) {
        float x = cval[j] - tau_lo;
        if (x > 0.0f) s += fast_pow(x, inv);
    }
    #pragma unroll
    for (int o = 16; o; o >>= 1) s += __shfl_xor_sync(0xFFFFFFFFu, s, o);
    if (lane == 0) red[w] = s;
    __syncthreads();
    float f_lo = -1.0f;
    #pragma unroll
    for (int i = 0; i < 16; i++) f_lo += red[i];
    __syncthreads();

    float tau_m = tau_lo;
    for (int it = 0; it < 50; it++) {
        dm *= 0.5f;
        tau_m = tau_lo + dm;
        s = 0.0f;
        for (int j = t; j < K; j += 512) {
            float x = cval[j] - tau_m;
            if (x > 0.0f) s += fast_pow(x, inv);
        }
        #pragma unroll
        for (int o = 16; o; o >>= 1) s += __shfl_xor_sync(0xFFFFFFFFu, s, o);
        if (lane == 0) red[w] = s;
        __syncthreads();
        float f_m = -1.0f;
        #pragma unroll
        for (int i = 0; i < 16; i++) f_m += red[i];
        __syncthreads();
        if (f_m * f_lo >= 0.0f) tau_lo = tau_m;
    }

    // final p and sum
    s = 0.0f;
    for (int j = t; j < K; j += 512) {
        float x = cval[j] - tau_m;
        float p = (x > 0.0f) ? fast_pow(x, inv) : 0.0f;
        cval[j] = p;
        s += p;
    }
    #pragma unroll
    for (int o = 16; o; o >>= 1) s += __shfl_xor_sync(0xFFFFFFFFu, s, o);
    if (lane == 0) red[w] = s;
    __syncthreads();
    float S = 0.0f;
    #pragma unroll
    for (int i = 0; i < 16; i++) S += red[i];
    __syncthreads();
    float invS = 1.0f / S;

    // sparse weighted sum over candidates
    int gq = t >> 7, d = t & 127;
    float acc = 0.0f;
    for (int j = gq; j < K; j += 4) {
        float wv = cval[j];
        if (wv != 0.0f) {
            int l = cidx[j];
            acc += wv * Rb[(size_t)l * ND + d];
        }
    }
    part[t] = acc;
    __syncthreads();

    float myr = 0.0f;
    if (t < ND) {
        float r = (part[t] + part[128 + t] + part[256 + t] + part[384 + t]) * invS;
        float e = (r > 0.0f) ? r : 1.6732632423543772f * expm1f(r);
        myr = 1.0507009873554805f * e;
    }
    float nsq = myr * myr;
    #pragma unroll
    for (int o = 16; o; o >>= 1) nsq += __shfl_xor_sync(0xFFFFFFFFu, nsq, o);
    if (lane == 0) red[w] = nsq;
    __syncthreads();
    float tot = 0.0f;
    #pragma unroll
    for (int i = 0; i < 16; i++) tot += red[i];
    if (t < ND) out[b * ND + t] = myr / sqrtf(tot);
}

// ============ launch ============
extern "C" void kernel_launch(void* const* d_in, const int* in_sizes, int n_in,
                              void* d_out, int out_size) {
    const float* R      = (const float*)d_in[0];
    const float* alpha  = (const float*)d_in[1];
    const float* target = (const float*)d_in[2];
    const float* Wr1    = (const float*)d_in[3];
    const float* Wr2    = (const float*)d_in[4];
    const float* Wr3    = (const float*)d_in[5];
    const float* bias_r = (const float*)d_in[6];
    const float* Wf_w   = (const float*)d_in[7];
    const float* Wf_b   = (const float*)d_in[8];
    float* out = (float*)d_out;

    int nsm = 0;
    cudaDeviceGetAttribute(&nsm, cudaDevAttrMultiProcessorCount, 0);
    if (nsm <= 0) nsm = 148;

    cudaFuncSetAttribute(k_gemm, cudaFuncAttributeMaxDynamicSharedMemorySize, SM_TOTAL);
    cudaFuncSetAttribute(k_entmax, cudaFuncAttributeMaxDynamicSharedMemorySize, E_TOTAL);

    k_prep<<<NB, 512>>>(target, Wf_w, Wf_b, Wr2, bias_r);
    k_gemm<<<nsm, 512, SM_TOTAL>>>(R, Wr1, Wr3);
    k_entmax<<<NB, 512, E_TOTAL>>>(R, alpha, Wr1, Wr3, out);
}

// round 17
// speedup vs baseline: 6.8123x; 6.8123x over previous
#include <cuda_runtime.h>
#include <cuda_fp16.h>
#include <cstdint>
#include <math.h>

#define NB 128
#define NL 4096
#define ND 128
#define NTILES 4096   // 128-row L tiles

// ---------------- scratch ----------------
__device__ float g_qb[NB * ND];
__device__ float g_scores[NB * NL];

__device__ __forceinline__ uint32_t smem_u32(const void* p) {
    uint32_t a;
    asm("{ .reg .u64 t; cvta.to.shared.u64 t, %1; cvt.u32.u64 %0, t; }" : "=r"(a) : "l"(p));
    return a;
}
__device__ __forceinline__ void ldsm_x4(uint32_t& r0, uint32_t& r1, uint32_t& r2, uint32_t& r3,
                                        uint32_t addr) {
    asm volatile("ldmatrix.sync.aligned.m8n8.x4.shared.b16 {%0,%1,%2,%3}, [%4];"
                 : "=r"(r0), "=r"(r1), "=r"(r2), "=r"(r3) : "r"(addr));
}
__device__ __forceinline__ void mma16816h(float* c, const uint32_t* a, const uint32_t* b) {
    asm volatile("mma.sync.aligned.m16n8k16.row.col.f32.f16.f16.f32 "
                 "{%0,%1,%2,%3}, {%4,%5,%6,%7}, {%8,%9}, {%0,%1,%2,%3};"
                 : "+f"(c[0]), "+f"(c[1]), "+f"(c[2]), "+f"(c[3])
                 : "r"(a[0]), "r"(a[1]), "r"(a[2]), "r"(a[3]), "r"(b[0]), "r"(b[1]));
}
__device__ __forceinline__ float fast_pow(float x, float e) {
    float l, r;
    asm("lg2.approx.f32 %0, %1;" : "=f"(l) : "f"(x));
    l *= e;
    asm("ex2.approx.f32 %0, %1;" : "=f"(r) : "f"(l));
    return r;
}
__device__ __forceinline__ uint32_t pack_h2(float x, float y) {
    __half h0 = __float2half_rn(x), h1 = __float2half_rn(y);
    return ((uint32_t)__half_as_ushort(h1) << 16) | __half_as_ushort(h0);
}

// ============ kernel 0: qb = Wr2·(Wf target + b) + bias_r ============
__global__ __launch_bounds__(512, 1)
void k_prep(const float* __restrict__ target, const float* __restrict__ Wf_w,
            const float* __restrict__ Wf_b, const float* __restrict__ Wr2,
            const float* __restrict__ bias_r) {
    int bx = blockIdx.x, t = threadIdx.x;
    int lane = t & 31, w = t >> 5;
    __shared__ float q[64];
    float4 tg4 = ((const float4*)(target + bx * ND))[lane];
    #pragma unroll
    for (int r = 0; r < 4; r++) {
        int e = w + r * 16;
        float4 wf = ((const float4*)(Wf_w + e * ND))[lane];
        float p = tg4.x * wf.x + tg4.y * wf.y + tg4.z * wf.z + tg4.w * wf.w;
        #pragma unroll
        for (int o = 16; o; o >>= 1) p += __shfl_xor_sync(0xFFFFFFFFu, p, o);
        if (lane == 0) q[e] = p + Wf_b[e];
    }
    __syncthreads();
    float2 q2 = ((const float2*)q)[lane];
    #pragma unroll
    for (int r = 0; r < 8; r++) {
        int d = w + r * 16;
        float2 w2 = ((const float2*)(Wr2 + d * 64))[lane];
        float p = q2.x * w2.x + q2.y * w2.y;
        #pragma unroll
        for (int o = 16; o; o >>= 1) p += __shfl_xor_sync(0xFFFFFFFFu, p, o);
        if (lane == 0) g_qb[bx * ND + d] = p + bias_r[d];
    }
}

// ============ kernel 1: persistent SINGLE-fp16 GEMM + fused score epilogue ============
// 512 threads (16 warps). Warp tile 32x32 (wr=w>>2, wc=w&3). 128-row L tiles.
#define ROWB 272
#define SA    0
#define SB_HI 34816
#define SM_PART 69632
#define SM_W3   71680
#define SM_TOTAL 72192

__device__ __forceinline__ void ldg_tile(float4* v, const float* __restrict__ R,
                                         int tile, int tid) {
    int b = tile >> 5, l0 = (tile & 31) << 7;
    const float4* src = (const float4*)(R + ((size_t)b * NL + l0) * ND);
    #pragma unroll
    for (int i = 0; i < 8; i++) v[i] = src[tid + i * 512];
}
__device__ __forceinline__ void cvt_store(char* smem, const float4* v, int tid) {
    #pragma unroll
    for (int i = 0; i < 8; i++) {
        int idx = tid + i * 512;
        int row = idx >> 5, c4 = idx & 31;
        float4 x = v[i];
        uint2 hp;
        hp.x = pack_h2(x.x, x.y);
        hp.y = pack_h2(x.z, x.w);
        *(uint2*)(smem + SA + row * ROWB + c4 * 8) = hp;
    }
}

__global__ __launch_bounds__(512, 1)
void k_gemm(const float* __restrict__ R, const float* __restrict__ Wr1,
            const float* __restrict__ Wr3) {
    extern __shared__ char smem[];
    uint32_t sb = smem_u32(smem);
    int tid = threadIdx.x, lane = tid & 31, w = tid >> 5;
    int wr = w >> 2, wc = w & 3;

    // ---- B tile (fp16 of Wr1) once per CTA ----
    {
        const float4* src = (const float4*)Wr1;
        #pragma unroll
        for (int i = 0; i < 8; i++) {
            int idx = tid + i * 512;
            int row = idx >> 5, c4 = idx & 31;
            float4 x = src[idx];
            uint2 hp;
            hp.x = pack_h2(x.x, x.y);
            hp.y = pack_h2(x.z, x.w);
            *(uint2*)(smem + SB_HI + row * ROWB + c4 * 8) = hp;
        }
        if (tid < ND) ((float*)(smem + SM_W3))[tid] = Wr3[tid];
    }

    uint32_t a_p = sb + SA + (wr * 32 + (lane & 15)) * ROWB + (lane >> 4) * 16;
    uint32_t b_p = sb + SB_HI + (wc * 32 + (lane >> 4) * 8 + (lane & 7)) * ROWB
                   + ((lane >> 3) & 1) * 16;

    int stride = gridDim.x;
    int t = blockIdx.x;
    float4 v[8];
    if (t < NTILES) {
        ldg_tile(v, R, t, tid);
        cvt_store(smem, v, tid);
    }

    while (t < NTILES) {
        __syncthreads();
        int tn = t + stride;
        if (tn < NTILES) ldg_tile(v, R, tn, tid);

        int b = t >> 5, l0 = (t & 31) << 7;

        float acc[2][4][4];
        #pragma unroll
        for (int mt = 0; mt < 2; mt++)
            #pragma unroll
            for (int nt = 0; nt < 4; nt++)
                #pragma unroll
                for (int k = 0; k < 4; k++) acc[mt][nt][k] = 0.0f;

        #pragma unroll
        for (int ks = 0; ks < 8; ks++) {
            uint32_t bh[4][2];
            ldsm_x4(bh[0][0], bh[0][1], bh[1][0], bh[1][1], b_p + ks * 32);
            ldsm_x4(bh[2][0], bh[2][1], bh[3][0], bh[3][1], b_p + 16 * ROWB + ks * 32);
            #pragma unroll
            for (int mt = 0; mt < 2; mt++) {
                uint32_t a4[4];
                ldsm_x4(a4[0], a4[1], a4[2], a4[3], a_p + mt * 16 * ROWB + ks * 32);
                #pragma unroll
                for (int nt = 0; nt < 4; nt++)
                    mma16816h(acc[mt][nt], a4, bh[nt]);
            }
        }

        // epilogue: score[m] = sum_c relu(h+qb)*w3
        {
            const float* w3s = (const float*)(smem + SM_W3);
            float* part = (float*)(smem + SM_PART);
            const float* qbb = g_qb + b * ND;
            int c0base = wc * 32 + (lane & 3) * 2;
            #pragma unroll
            for (int mt = 0; mt < 2; mt++) {
                float vlo = 0.0f, vhi = 0.0f;
                #pragma unroll
                for (int nt = 0; nt < 4; nt++) {
                    int c0 = c0base + nt * 8, c1 = c0 + 1;
                    float q0 = __ldg(qbb + c0), q1 = __ldg(qbb + c1);
                    float t0 = w3s[c0], t1 = w3s[c1];
                    vlo += fmaxf(acc[mt][nt][0] + q0, 0.0f) * t0
                         + fmaxf(acc[mt][nt][1] + q1, 0.0f) * t1;
                    vhi += fmaxf(acc[mt][nt][2] + q0, 0.0f) * t0
                         + fmaxf(acc[mt][nt][3] + q1, 0.0f) * t1;
                }
                vlo += __shfl_xor_sync(0xFFFFFFFFu, vlo, 1);
                vlo += __shfl_xor_sync(0xFFFFFFFFu, vlo, 2);
                vhi += __shfl_xor_sync(0xFFFFFFFFu, vhi, 1);
                vhi += __shfl_xor_sync(0xFFFFFFFFu, vhi, 2);
                if ((lane & 3) == 0) {
                    int rlo = wr * 32 + mt * 16 + (lane >> 2);
                    part[rlo * 4 + wc] = vlo;
                    part[(rlo + 8) * 4 + wc] = vhi;
                }
            }
        }
        __syncthreads();
        if (tid < 128) {
            const float* part = (const float*)(smem + SM_PART);
            float s = part[tid * 4] + part[tid * 4 + 1] + part[tid * 4 + 2] + part[tid * 4 + 3];
            g_scores[b * NL + l0 + tid] = s;
        }
        if (tn < NTILES) cvt_store(smem, v, tid);
        t = tn;
    }
}

// ============ kernel 2: entmax bisection (compacted, 32 iters) + weighted sum ============
__global__ __launch_bounds__(512, 1)
void k_entmax(const float* __restrict__ R, const float* __restrict__ alpha,
              float* __restrict__ out) {
    __shared__ float cval[NL];
    __shared__ unsigned short cidx[NL];
    __shared__ float red[16];
    __shared__ int cnt;
    __shared__ float part[512];

    int b = blockIdx.x, t = threadIdx.x;
    int lane = t & 31, w = t >> 5;
    float am1 = alpha[b] - 1.0f;
    float inv = 1.0f / am1;

    if (t == 0) cnt = 0;

    float v[8];
    float mx = -3.4e38f;
    #pragma unroll
    for (int i = 0; i < 8; i++) {
        v[i] = g_scores[b * NL + t + i * 512] * am1;
        mx = fmaxf(mx, v[i]);
    }
    #pragma unroll
    for (int o = 16; o; o >>= 1) mx = fmaxf(mx, __shfl_xor_sync(0xFFFFFFFFu, mx, o));
    if (lane == 0) red[w] = mx;
    __syncthreads();
    mx = red[0];
    #pragma unroll
    for (int i = 1; i < 16; i++) mx = fmaxf(mx, red[i]);
    __syncthreads();

    // compact candidates: only Xs > mx-1 can ever have p > 0 (tau >= mx-1 always)
    float thr = mx - 1.0f;
    #pragma unroll
    for (int i = 0; i < 8; i++) {
        bool p = v[i] > thr;
        unsigned m = __ballot_sync(0xFFFFFFFFu, p);
        int base = 0;
        if (lane == 0 && m) base = atomicAdd(&cnt, __popc(m));
        base = __shfl_sync(0xFFFFFFFFu, base, 0);
        if (p) {
            int off = base + __popc(m & ((1u << lane) - 1u));
            cval[off] = v[i];
            cidx[off] = (unsigned short)(t + i * 512);
        }
    }
    __syncthreads();
    int K = cnt;

    float tau_lo = mx - 1.0f;
    float tau_hi = mx - exp2f(-12.0f * am1);
    float dm = tau_hi - tau_lo;

    float s = 0.0f;
    for (int j = t; j < K; j += 512) {
        float x = cval[j] - tau_lo;
        if (x > 0.0f) s += fast_pow(x, inv);
    }
    #pragma unroll
    for (int o = 16; o; o >>= 1) s += __shfl_xor_sync(0xFFFFFFFFu, s, o);
    if (lane == 0) red[w] = s;
    __syncthreads();
    float f_lo = -1.0f;
    #pragma unroll
    for (int i = 0; i < 16; i++) f_lo += red[i];
    __syncthreads();

    float tau_m = tau_lo;
    for (int it = 0; it < 32; it++) {       // converged value matters, not trajectory
        dm *= 0.5f;
        tau_m = tau_lo + dm;
        s = 0.0f;
        for (int j = t; j < K; j += 512) {
            float x = cval[j] - tau_m;
            if (x > 0.0f) s += fast_pow(x, inv);
        }
        #pragma unroll
        for (int o = 16; o; o >>= 1) s += __shfl_xor_sync(0xFFFFFFFFu, s, o);
        if (lane == 0) red[w] = s;
        __syncthreads();
        float f_m = -1.0f;
        #pragma unroll
        for (int i = 0; i < 16; i++) f_m += red[i];
        __syncthreads();
        if (f_m * f_lo >= 0.0f) tau_lo = tau_m;
    }

    s = 0.0f;
    for (int j = t; j < K; j += 512) {
        float x = cval[j] - tau_m;
        float p = (x > 0.0f) ? fast_pow(x, inv) : 0.0f;
        cval[j] = p;
        s += p;
    }
    #pragma unroll
    for (int o = 16; o; o >>= 1) s += __shfl_xor_sync(0xFFFFFFFFu, s, o);
    if (lane == 0) red[w] = s;
    __syncthreads();
    float S = 0.0f;
    #pragma unroll
    for (int i = 0; i < 16; i++) S += red[i];
    __syncthreads();
    float invS = 1.0f / S;

    int gq = t >> 7, d = t & 127;
    const float* Rb = R + (size_t)b * NL * ND;
    float acc = 0.0f;
    for (int j = gq; j < K; j += 4) {
        float wv = cval[j];
        if (wv != 0.0f) {
            int l = cidx[j];
            acc += wv * Rb[(size_t)l * ND + d];
        }
    }
    part[t] = acc;
    __syncthreads();

    float myr = 0.0f;
    if (t < ND) {
        float r = (part[t] + part[128 + t] + part[256 + t] + part[384 + t]) * invS;
        float e = (r > 0.0f) ? r : 1.6732632423543772f * expm1f(r);
        myr = 1.0507009873554805f * e;
    }
    float nsq = myr * myr;
    #pragma unroll
    for (int o = 16; o; o >>= 1) nsq += __shfl_xor_sync(0xFFFFFFFFu, nsq, o);
    if (lane == 0) red[w] = nsq;
    __syncthreads();
    float tot = 0.0f;
    #pragma unroll
    for (int i = 0; i < 16; i++) tot += red[i];
    if (t < ND) out[b * ND + t] = myr / sqrtf(tot);
}

// ============ launch ============
extern "C" void kernel_launch(void* const* d_in, const int* in_sizes, int n_in,
                              void* d_out, int out_size) {
    const float* R      = (const float*)d_in[0];
    const float* alpha  = (const float*)d_in[1];
    const float* target = (const float*)d_in[2];
    const float* Wr1    = (const float*)d_in[3];
    const float* Wr2    = (const float*)d_in[4];
    const float* Wr3    = (const float*)d_in[5];
    const float* bias_r = (const float*)d_in[6];
    const float* Wf_w   = (const float*)d_in[7];
    const float* Wf_b   = (const float*)d_in[8];
    float* out = (float*)d_out;

    int nsm = 0;
    cudaDeviceGetAttribute(&nsm, cudaDevAttrMultiProcessorCount, 0);
    if (nsm <= 0) nsm = 148;

    cudaFuncSetAttribute(k_gemm, cudaFuncAttributeMaxDynamicSharedMemorySize, SM_TOTAL);

    k_prep<<<NB, 512>>>(target, Wf_w, Wf_b, Wr2, bias_r);
    k_gemm<<<nsm, 512, SM_TOTAL>>>(R, Wr1, Wr3);
    k_entmax<<<NB, 512>>>(R, alpha, out);
}